// round 16
// baseline (speedup 1.0000x reference)
#include <cuda_runtime.h>
#include <cuda_fp16.h>
#include <cstdint>

// Problem dims
#define N_SAMPLES 2048
#define D_FEAT    64
#define P_PAIRS   2016
#define INNER     32
#define KDIM      64512   // P_PAIRS * INNER
#define HIDDEN    2048
#define CLASSES   10

// GEMM tiling
#define BM 128
#define BN 256
#define BK 64
#define STG 4
#define CHUNKS (KDIM / BK)                 // 1008
#define A_STAGE (BM * 128)                 // 16384 B
#define B_STAGE (BN * 128)                 // 32768 B
#define STAGE_B (A_STAGE + B_STAGE)        // 49152 B
#define OFF_MBAR (STG * STAGE_B)           // 196608
#define SMEM_GEMM (OFF_MBAR + 64)

// split-K persistent schedule
#define NSM      148
#define KSLICES  8
#define NTILES   128                       // 16 mb x 8 nb
#define UNITS    (NTILES * KSLICES)        // 1024
#define UCHUNKS  (CHUNKS / KSLICES)        // 126
#define TILE_ELEMS (BM * BN)               // 32768

// -------------------- scratch (device globals; no allocation) --------------------
__device__ __half g_u   [(size_t)N_SAMPLES * KDIM];   // tiled [mb][c][row][kc^sw]
__device__ __half g_bt  [(size_t)HIDDEN    * KDIM];   // tiled [nb][c][row][kc^sw]
__device__ float  g_part[(size_t)UNITS * TILE_ELEMS]; // 134 MB split-K partials

// -------------------- helpers --------------------
__device__ __forceinline__ uint32_t smem_u32(const void* p) {
    return (uint32_t)__cvta_generic_to_shared(p);
}
__device__ __forceinline__ void mbar_init(uint32_t addr, uint32_t count) {
    asm volatile("mbarrier.init.shared.b64 [%0], %1;" :: "r"(addr), "r"(count) : "memory");
}
__device__ __forceinline__ void mbar_expect_tx(uint32_t addr, uint32_t bytes) {
    asm volatile("mbarrier.arrive.expect_tx.shared.b64 _, [%0], %1;"
                 :: "r"(addr), "r"(bytes) : "memory");
}
__device__ __forceinline__ void mbar_arrive(uint32_t addr) {
    asm volatile("mbarrier.arrive.shared.b64 _, [%0];" :: "r"(addr) : "memory");
}
__device__ __forceinline__ void mbar_wait(uint32_t addr, uint32_t parity) {
    uint32_t done;
    asm volatile(
        "{\n\t.reg .pred p;\n\t"
        "mbarrier.try_wait.parity.acquire.cta.shared::cta.b64 p, [%1], %2;\n\t"
        "selp.b32 %0, 1, 0, p;\n\t}"
        : "=r"(done) : "r"(addr), "r"(parity) : "memory");
    if (!done) {
        asm volatile(
            "{\n\t.reg .pred P1;\n\t"
            "W_%=:\n\t"
            "mbarrier.try_wait.parity.acquire.cta.shared::cta.b64 P1, [%0], %1, 0x989680;\n\t"
            "@P1 bra.uni D_%=;\n\t"
            "bra.uni W_%=;\n\t"
            "D_%=:\n\t}"
            :: "r"(addr), "r"(parity) : "memory");
    }
}
__device__ __forceinline__ void bulk_g2s(uint32_t dstSmem, const void* srcGmem,
                                         uint32_t bytes, uint32_t mbar) {
    asm volatile(
        "cp.async.bulk.shared::cluster.global.mbarrier::complete_tx::bytes [%0], [%1], %2, [%3];"
        :: "r"(dstSmem), "l"(srcGmem), "r"(bytes), "r"(mbar) : "memory");
}
__device__ __forceinline__ void ldsm_x4(uint32_t* r, uint32_t addr) {
    asm volatile("ldmatrix.sync.aligned.m8n8.x4.shared.b16 {%0,%1,%2,%3}, [%4];"
                 : "=r"(r[0]), "=r"(r[1]), "=r"(r[2]), "=r"(r[3]) : "r"(addr));
}
__device__ __forceinline__ void mma16816(float* c, const uint32_t* a, const uint32_t* b) {
    asm volatile(
        "mma.sync.aligned.m16n8k16.row.col.f32.f16.f16.f32 "
        "{%0,%1,%2,%3}, {%4,%5,%6,%7}, {%8,%9}, {%0,%1,%2,%3};"
        : "+f"(c[0]), "+f"(c[1]), "+f"(c[2]), "+f"(c[3])
        : "r"(a[0]), "r"(a[1]), "r"(a[2]), "r"(a[3]), "r"(b[0]), "r"(b[1]));
}
__device__ __forceinline__ uint32_t sw_off(int row, int kc) {
    return (uint32_t)(row * 128 + ((kc ^ (row & 7)) << 4));
}

// ==================== kernel 1 (fused): pairwise MLP + Wv transpose/convert ====================
#define CONV_BLOCKS (CHUNKS * (HIDDEN / 64))   // 32256

__global__ void k_prep(const float* __restrict__ x, const float* __restrict__ Wu,
                       const float* __restrict__ bu, const float* __restrict__ Wv) {
    int tid = threadIdx.x;
    if (blockIdx.x < CHUNKS) {
        // ---- pairs: chunk c = pairs 2c, 2c+1; lane kc = tid&7 owns one 16B unit per row ----
        int c = blockIdx.x;
        int kc = tid & 7;
        int pp = kc >> 2;
        int p = c * 2 + pp;
        int i0 = (kc & 3) * 8;
        int a = 0, rem = p;
        while (rem >= (D_FEAT - 1 - a)) { rem -= (D_FEAT - 1 - a); a++; }
        int b = a + 1 + rem;
        float w0v[8], w1v[8], bbv[8];
        #pragma unroll
        for (int j = 0; j < 8; j++) {
            w0v[j] = __ldg(Wu + (size_t)p * 64 + i0 + j);
            w1v[j] = __ldg(Wu + (size_t)p * 64 + 32 + i0 + j);
            bbv[j] = __ldg(bu + (size_t)p * 32 + i0 + j);
        }
        uint4* g_u_u4 = reinterpret_cast<uint4*>(g_u);
        int rbase = tid >> 3;
        #pragma unroll 1
        for (int pass = 0; pass < 64; pass++) {
            int n = pass * 32 + rbase;
            float va = __ldg(x + (size_t)n * D_FEAT + a);
            float vb = __ldg(x + (size_t)n * D_FEAT + b);
            __half2 ov[4];
            #pragma unroll
            for (int j = 0; j < 8; j += 2) {
                float r0 = fmaf(va, w0v[j],     fmaf(vb, w1v[j],     bbv[j]));
                float r1 = fmaf(va, w0v[j + 1], fmaf(vb, w1v[j + 1], bbv[j + 1]));
                ov[j >> 1] = __floats2half2_rn(fmaxf(r0, 0.f), fmaxf(r1, 0.f));
            }
            int mb = n >> 7, row = n & 127;
            size_t unit = ((size_t)(mb * CHUNKS + c) * 128 + row) * 8 + (kc ^ (row & 7));
            g_u_u4[unit] = *reinterpret_cast<uint4*>(ov);
        }
    } else {
        // ---- conv: chunk c (64 k-rows) x 64 n, float4 loads, single barrier ----
        int bid = blockIdx.x - CHUNKS;
        int c = bid >> 5;
        int nt0 = (bid & 31) * 64;
        __shared__ float tile[64][65];
        #pragma unroll
        for (int p4 = 0; p4 < 4; p4++) {
            int idx = tid + p4 * 256;
            int kl = idx >> 4, c4 = idx & 15;
            float4 v = *reinterpret_cast<const float4*>(
                Wv + (size_t)(c * 64 + kl) * HIDDEN + nt0 + c4 * 4);
            tile[kl][c4 * 4 + 0] = v.x;
            tile[kl][c4 * 4 + 1] = v.y;
            tile[kl][c4 * 4 + 2] = v.z;
            tile[kl][c4 * 4 + 3] = v.w;
        }
        __syncthreads();
        int nl = tid >> 2, uq = tid & 3;
        int n = nt0 + nl;
        int nb = n >> 8, rowB = n & 255;
        size_t base8 = ((size_t)(nb * CHUNKS + c) * 256 + rowB) * 8;
        #pragma unroll
        for (int h = 0; h < 2; h++) {
            int kc = uq + h * 4;
            __half hp[8];
            #pragma unroll
            for (int j = 0; j < 8; j++) hp[j] = __float2half(tile[kc * 8 + j][nl]);
            reinterpret_cast<uint4*>(g_bt)[base8 + (kc ^ (rowB & 7))] =
                *reinterpret_cast<uint4*>(hp);
        }
    }
}

// ==================== kernel 2: persistent split-K GEMM (148 CTAs, 1024 units) ====================
__global__ void __launch_bounds__(512, 1) k_gemm() {
    extern __shared__ char smem[];
    uint32_t sbase = smem_u32(smem);
    int tid = threadIdx.x;
    int lane = tid & 31;
    int wid = tid >> 5;          // 0..15
    int wm = wid >> 3;           // 0..1  (64 rows)
    int wn = wid & 7;            // 0..7  (32 cols)
    int bid = blockIdx.x;        // 0..147

    int nUnits = (UNITS - 1 - bid) / NSM + 1;
    int Qtot = nUnits * UCHUNKS;

    uint32_t mfull = sbase + OFF_MBAR;
    uint32_t mempty = sbase + OFF_MBAR + 32;
    if (tid == 0) {
        #pragma unroll
        for (int s = 0; s < STG; s++) {
            mbar_init(mfull + s * 8, 1);
            mbar_init(mempty + s * 8, 16);
        }
    }
    __syncthreads();

    if (tid == 0) {
        int t0 = bid >> 3;
        int mb0 = t0 >> 3, nb0 = t0 & 7, ks0 = bid & 7;
        #pragma unroll
        for (int s = 0; s < STG - 1; s++) {
            int cc = ks0 * UCHUNKS + s;
            const char* aP = (const char*)g_u  + ((size_t)mb0 * CHUNKS + cc) * A_STAGE;
            const char* bP = (const char*)g_bt + ((size_t)nb0 * CHUNKS + cc) * B_STAGE;
            mbar_expect_tx(mfull + s * 8, STAGE_B);
            bulk_g2s(sbase + s * STAGE_B,           aP, A_STAGE, mfull + s * 8);
            bulk_g2s(sbase + s * STAGE_B + A_STAGE, bP, B_STAGE, mfull + s * 8);
        }
    }

    int g = lane >> 3, sub = lane & 7;
    int rowA_base = wm * 64 + ((g & 1) << 3) + sub;
    int kcA_base  = g >> 1;
    int rowB_base = wn * 32 + ((g >> 1) << 3) + sub;
    int kcB_base  = g & 1;

    float acc[4][4][4];
    #pragma unroll
    for (int i = 0; i < 4; i++)
        #pragma unroll
        for (int j = 0; j < 4; j++)
            #pragma unroll
            for (int t = 0; t < 4; t++) acc[i][j][t] = 0.f;

    int rlo = lane >> 2;
    int cpair = (lane & 3) * 2;
    int cIn = 0;
    int unitIdx = 0;

    for (int q = 0; q < Qtot; q++) {
        int slot = q & 3;
        if (wid == 0) {
            int qp = q + STG - 1;
            if (qp < Qtot) {
                int sp = qp & 3;
                if (qp >= STG) mbar_wait(mempty + sp * 8, ((qp >> 2) + 1) & 1);
                if (lane == 0) {
                    int u = bid + NSM * (qp / UCHUNKS);
                    int t = u >> 3;
                    int cc = (u & 7) * UCHUNKS + (qp % UCHUNKS);
                    const char* aP = (const char*)g_u  + ((size_t)(t >> 3) * CHUNKS + cc) * A_STAGE;
                    const char* bP = (const char*)g_bt + ((size_t)(t & 7)  * CHUNKS + cc) * B_STAGE;
                    mbar_expect_tx(mfull + sp * 8, STAGE_B);
                    bulk_g2s(sbase + sp * STAGE_B,           aP, A_STAGE, mfull + sp * 8);
                    bulk_g2s(sbase + sp * STAGE_B + A_STAGE, bP, B_STAGE, mfull + sp * 8);
                }
            }
        }

        mbar_wait(mfull + slot * 8, (q >> 2) & 1);

        uint32_t aS = sbase + slot * STAGE_B;
        uint32_t bS = aS + A_STAGE;
        #pragma unroll
        for (int ks = 0; ks < 4; ks++) {
            uint32_t afr[4][4], bfr[2][4];
            #pragma unroll
            for (int qq = 0; qq < 2; qq++) {
                int row = rowB_base + qq * 16;
                ldsm_x4(bfr[qq], bS + sw_off(row, ks * 2 + kcB_base));
            }
            #pragma unroll
            for (int mt = 0; mt < 4; mt++) {
                int row = rowA_base + mt * 16;
                ldsm_x4(afr[mt], aS + sw_off(row, ks * 2 + kcA_base));
            }
            #pragma unroll
            for (int mt = 0; mt < 4; mt++)
                #pragma unroll
                for (int nt = 0; nt < 4; nt++)
                    mma16816(acc[mt][nt], afr[mt], &bfr[nt >> 1][(nt & 1) * 2]);
        }
        if (lane == 0) mbar_arrive(mempty + slot * 8);

        if (++cIn == UCHUNKS) {
            cIn = 0;
            int u = bid + NSM * unitIdx;
            unitIdx++;
            float* dst = g_part + (size_t)u * TILE_ELEMS;
            #pragma unroll
            for (int mt = 0; mt < 4; mt++) {
                #pragma unroll
                for (int nt = 0; nt < 4; nt++) {
                    int col = wn * 32 + nt * 8 + cpair;
                    int row0 = wm * 64 + mt * 16 + rlo;
                    *reinterpret_cast<float2*>(dst + (size_t)row0 * BN + col) =
                        make_float2(acc[mt][nt][0], acc[mt][nt][1]);
                    *reinterpret_cast<float2*>(dst + (size_t)(row0 + 8) * BN + col) =
                        make_float2(acc[mt][nt][2], acc[mt][nt][3]);
                    acc[mt][nt][0] = acc[mt][nt][1] = acc[mt][nt][2] = acc[mt][nt][3] = 0.f;
                }
            }
        }
    }
}

// ==================== kernel 3: fused reduce + bias + relu + head ====================
// 256 blocks x 8 samples. v[n][h] = relu(bv[h] + sum_ks part) computed inline from
// split-K partials (warp-coalesced per slice), then 10-class dot with Wo.
__global__ void __launch_bounds__(256) k_final(const float* __restrict__ bv,
                                               const float* __restrict__ Wo,
                                               const float* __restrict__ bo,
                                               float* __restrict__ out) {
    int n0 = blockIdx.x * 8;     // 256 blocks; all 8 samples share mb = n0>>7
    int tid = threadIdx.x;
    int lane = tid & 31, wid = tid >> 5;
    int mb = n0 >> 7;

    float acc[8][CLASSES];
    #pragma unroll
    for (int s = 0; s < 8; s++)
        #pragma unroll
        for (int c = 0; c < CLASSES; c++) acc[s][c] = 0.f;

    for (int h = tid; h < HIDDEN; h += 256) {
        float w[CLASSES];
        const float2* wrow = reinterpret_cast<const float2*>(Wo + (size_t)h * CLASSES);
        #pragma unroll
        for (int c2 = 0; c2 < CLASSES / 2; c2++) {
            float2 ww = __ldg(wrow + c2);
            w[c2 * 2] = ww.x; w[c2 * 2 + 1] = ww.y;
        }
        float bias = __ldg(bv + h);
        int nb = h >> 8, col = h & 255;
        int tile = mb * 8 + nb;
        const float* pbase = g_part + ((size_t)tile * KSLICES) * TILE_ELEMS + col;
        #pragma unroll
        for (int s = 0; s < 8; s++) {
            int row = (n0 + s) & 127;
            const float* p = pbase + (size_t)row * BN;
            float v = bias;
            #pragma unroll
            for (int ks = 0; ks < KSLICES; ks++)
                v += __ldg(p + (size_t)ks * TILE_ELEMS);
            v = fmaxf(v, 0.f);
            #pragma unroll
            for (int c = 0; c < CLASSES; c++) acc[s][c] = fmaf(v, w[c], acc[s][c]);
        }
    }
    #pragma unroll
    for (int s = 0; s < 8; s++)
        #pragma unroll
        for (int c = 0; c < CLASSES; c++)
            #pragma unroll
            for (int o = 16; o > 0; o >>= 1)
                acc[s][c] += __shfl_xor_sync(0xffffffffu, acc[s][c], o);

    __shared__ float part[8][8][CLASSES];
    if (lane == 0) {
        #pragma unroll
        for (int s = 0; s < 8; s++)
            #pragma unroll
            for (int c = 0; c < CLASSES; c++) part[wid][s][c] = acc[s][c];
    }
    __syncthreads();
    if (tid < 8 * CLASSES) {
        int s = tid / CLASSES, c = tid % CLASSES;
        float sum = 0.f;
        #pragma unroll
        for (int w = 0; w < 8; w++) sum += part[w][s][c];
        out[(size_t)(n0 + s) * CLASSES + c] = sum + bo[c];
    }
}

// ==================== launch ====================
extern "C" void kernel_launch(void* const* d_in, const int* in_sizes, int n_in,
                              void* d_out, int out_size) {
    const float* x  = (const float*)d_in[0];
    const float* Wu = (const float*)d_in[1];
    const float* bu = (const float*)d_in[2];
    const float* Wv = (const float*)d_in[3];
    const float* bv = (const float*)d_in[4];
    const float* Wo = (const float*)d_in[5];
    const float* bo = (const float*)d_in[6];
    float* out = (float*)d_out;

    cudaFuncSetAttribute(k_gemm, cudaFuncAttributeMaxDynamicSharedMemorySize, SMEM_GEMM);

    k_prep<<<CHUNKS + CONV_BLOCKS, 256>>>(x, Wu, bu, Wv);
    k_gemm<<<NSM, 512, SMEM_GEMM>>>();
    k_final<<<N_SAMPLES / 8, 256>>>(bv, Wo, bo, out);
}

// round 17
// speedup vs baseline: 1.0134x; 1.0134x over previous
#include <cuda_runtime.h>
#include <cuda_fp16.h>
#include <cstdint>

// Problem dims
#define N_SAMPLES 2048
#define D_FEAT    64
#define P_PAIRS   2016
#define INNER     32
#define KDIM      64512   // P_PAIRS * INNER
#define HIDDEN    2048
#define CLASSES   10

// GEMM tiling
#define BM 128
#define BN 256
#define BK 64
#define STG 4
#define CHUNKS (KDIM / BK)                 // 1008
#define A_STAGE (BM * 128)                 // 16384 B
#define B_STAGE (BN * 128)                 // 32768 B
#define STAGE_B (A_STAGE + B_STAGE)        // 49152 B
#define OFF_MBAR (STG * STAGE_B)           // 196608
#define SMEM_GEMM (OFF_MBAR + 64)

// split-K persistent schedule
#define NSM      148
#define KSLICES  8
#define NTILES   128                       // 16 mb x 8 nb
#define UNITS    (NTILES * KSLICES)        // 1024
#define UCHUNKS  (CHUNKS / KSLICES)        // 126
#define TILE_ELEMS (BM * BN)               // 32768

// -------------------- scratch (device globals; no allocation) --------------------
__device__ __half g_u   [(size_t)N_SAMPLES * KDIM];   // tiled [mb][c][row][kc^sw]
__device__ __half g_bt  [(size_t)HIDDEN    * KDIM];   // tiled [nb][c][row][kc^sw]
__device__ float  g_part[(size_t)UNITS * TILE_ELEMS]; // 134 MB split-K partials

// -------------------- helpers --------------------
__device__ __forceinline__ uint32_t smem_u32(const void* p) {
    return (uint32_t)__cvta_generic_to_shared(p);
}
__device__ __forceinline__ void mbar_init(uint32_t addr, uint32_t count) {
    asm volatile("mbarrier.init.shared.b64 [%0], %1;" :: "r"(addr), "r"(count) : "memory");
}
__device__ __forceinline__ void mbar_expect_tx(uint32_t addr, uint32_t bytes) {
    asm volatile("mbarrier.arrive.expect_tx.shared.b64 _, [%0], %1;"
                 :: "r"(addr), "r"(bytes) : "memory");
}
__device__ __forceinline__ void mbar_arrive(uint32_t addr) {
    asm volatile("mbarrier.arrive.shared.b64 _, [%0];" :: "r"(addr) : "memory");
}
__device__ __forceinline__ void mbar_wait(uint32_t addr, uint32_t parity) {
    uint32_t done;
    asm volatile(
        "{\n\t.reg .pred p;\n\t"
        "mbarrier.try_wait.parity.acquire.cta.shared::cta.b64 p, [%1], %2;\n\t"
        "selp.b32 %0, 1, 0, p;\n\t}"
        : "=r"(done) : "r"(addr), "r"(parity) : "memory");
    if (!done) {
        asm volatile(
            "{\n\t.reg .pred P1;\n\t"
            "W_%=:\n\t"
            "mbarrier.try_wait.parity.acquire.cta.shared::cta.b64 P1, [%0], %1, 0x989680;\n\t"
            "@P1 bra.uni D_%=;\n\t"
            "bra.uni W_%=;\n\t"
            "D_%=:\n\t}"
            :: "r"(addr), "r"(parity) : "memory");
    }
}
__device__ __forceinline__ void bulk_g2s(uint32_t dstSmem, const void* srcGmem,
                                         uint32_t bytes, uint32_t mbar) {
    asm volatile(
        "cp.async.bulk.shared::cluster.global.mbarrier::complete_tx::bytes [%0], [%1], %2, [%3];"
        :: "r"(dstSmem), "l"(srcGmem), "r"(bytes), "r"(mbar) : "memory");
}
__device__ __forceinline__ void ldsm_x4(uint32_t* r, uint32_t addr) {
    asm volatile("ldmatrix.sync.aligned.m8n8.x4.shared.b16 {%0,%1,%2,%3}, [%4];"
                 : "=r"(r[0]), "=r"(r[1]), "=r"(r[2]), "=r"(r[3]) : "r"(addr));
}
__device__ __forceinline__ void mma16816(float* c, const uint32_t* a, const uint32_t* b) {
    asm volatile(
        "mma.sync.aligned.m16n8k16.row.col.f32.f16.f16.f32 "
        "{%0,%1,%2,%3}, {%4,%5,%6,%7}, {%8,%9}, {%0,%1,%2,%3};"
        : "+f"(c[0]), "+f"(c[1]), "+f"(c[2]), "+f"(c[3])
        : "r"(a[0]), "r"(a[1]), "r"(a[2]), "r"(a[3]), "r"(b[0]), "r"(b[1]));
}
__device__ __forceinline__ uint32_t sw_off(int row, int kc) {
    return (uint32_t)(row * 128 + ((kc ^ (row & 7)) << 4));
}

// ==================== kernel 1 (fused): pairwise MLP + Wv transpose/convert ====================
#define CONV_BLOCKS (CHUNKS * (HIDDEN / 64))   // 32256

__global__ void k_prep(const float* __restrict__ x, const float* __restrict__ Wu,
                       const float* __restrict__ bu, const float* __restrict__ Wv) {
    int tid = threadIdx.x;
    if (blockIdx.x < CHUNKS) {
        // ---- pairs: chunk c = pairs 2c, 2c+1; lane kc = tid&7 owns one 16B unit per row ----
        int c = blockIdx.x;
        int kc = tid & 7;
        int pp = kc >> 2;
        int p = c * 2 + pp;
        int i0 = (kc & 3) * 8;
        int a = 0, rem = p;
        while (rem >= (D_FEAT - 1 - a)) { rem -= (D_FEAT - 1 - a); a++; }
        int b = a + 1 + rem;
        float w0v[8], w1v[8], bbv[8];
        #pragma unroll
        for (int j = 0; j < 8; j++) {
            w0v[j] = __ldg(Wu + (size_t)p * 64 + i0 + j);
            w1v[j] = __ldg(Wu + (size_t)p * 64 + 32 + i0 + j);
            bbv[j] = __ldg(bu + (size_t)p * 32 + i0 + j);
        }
        uint4* g_u_u4 = reinterpret_cast<uint4*>(g_u);
        int rbase = tid >> 3;
        #pragma unroll 1
        for (int pass = 0; pass < 64; pass++) {
            int n = pass * 32 + rbase;
            float va = __ldg(x + (size_t)n * D_FEAT + a);
            float vb = __ldg(x + (size_t)n * D_FEAT + b);
            __half2 ov[4];
            #pragma unroll
            for (int j = 0; j < 8; j += 2) {
                float r0 = fmaf(va, w0v[j],     fmaf(vb, w1v[j],     bbv[j]));
                float r1 = fmaf(va, w0v[j + 1], fmaf(vb, w1v[j + 1], bbv[j + 1]));
                ov[j >> 1] = __floats2half2_rn(fmaxf(r0, 0.f), fmaxf(r1, 0.f));
            }
            int mb = n >> 7, row = n & 127;
            size_t unit = ((size_t)(mb * CHUNKS + c) * 128 + row) * 8 + (kc ^ (row & 7));
            g_u_u4[unit] = *reinterpret_cast<uint4*>(ov);
        }
    } else {
        // ---- conv: chunk c (64 k-rows) x 64 n, float4 loads, single barrier ----
        int bid = blockIdx.x - CHUNKS;
        int c = bid >> 5;
        int nt0 = (bid & 31) * 64;
        __shared__ float tile[64][65];
        #pragma unroll
        for (int p4 = 0; p4 < 4; p4++) {
            int idx = tid + p4 * 256;
            int kl = idx >> 4, c4 = idx & 15;
            float4 v = *reinterpret_cast<const float4*>(
                Wv + (size_t)(c * 64 + kl) * HIDDEN + nt0 + c4 * 4);
            tile[kl][c4 * 4 + 0] = v.x;
            tile[kl][c4 * 4 + 1] = v.y;
            tile[kl][c4 * 4 + 2] = v.z;
            tile[kl][c4 * 4 + 3] = v.w;
        }
        __syncthreads();
        int nl = tid >> 2, uq = tid & 3;
        int n = nt0 + nl;
        int nb = n >> 8, rowB = n & 255;
        size_t base8 = ((size_t)(nb * CHUNKS + c) * 256 + rowB) * 8;
        #pragma unroll
        for (int h = 0; h < 2; h++) {
            int kc = uq + h * 4;
            __half hp[8];
            #pragma unroll
            for (int j = 0; j < 8; j++) hp[j] = __float2half(tile[kc * 8 + j][nl]);
            reinterpret_cast<uint4*>(g_bt)[base8 + (kc ^ (rowB & 7))] =
                *reinterpret_cast<uint4*>(hp);
        }
    }
}

// ==================== kernel 2: persistent split-K GEMM (148 CTAs, 1024 units) ====================
__global__ void __launch_bounds__(512, 1) k_gemm() {
    extern __shared__ char smem[];
    uint32_t sbase = smem_u32(smem);
    int tid = threadIdx.x;
    int lane = tid & 31;
    int wid = tid >> 5;          // 0..15
    int wm = wid >> 3;           // 0..1  (64 rows)
    int wn = wid & 7;            // 0..7  (32 cols)
    int bid = blockIdx.x;        // 0..147

    int nUnits = (UNITS - 1 - bid) / NSM + 1;
    int Qtot = nUnits * UCHUNKS;

    uint32_t mfull = sbase + OFF_MBAR;
    uint32_t mempty = sbase + OFF_MBAR + 32;
    if (tid == 0) {
        #pragma unroll
        for (int s = 0; s < STG; s++) {
            mbar_init(mfull + s * 8, 1);
            mbar_init(mempty + s * 8, 16);
        }
    }
    __syncthreads();

    if (tid == 0) {
        int t0 = bid >> 3;
        int mb0 = t0 >> 3, nb0 = t0 & 7, ks0 = bid & 7;
        #pragma unroll
        for (int s = 0; s < STG - 1; s++) {
            int cc = ks0 * UCHUNKS + s;
            const char* aP = (const char*)g_u  + ((size_t)mb0 * CHUNKS + cc) * A_STAGE;
            const char* bP = (const char*)g_bt + ((size_t)nb0 * CHUNKS + cc) * B_STAGE;
            mbar_expect_tx(mfull + s * 8, STAGE_B);
            bulk_g2s(sbase + s * STAGE_B,           aP, A_STAGE, mfull + s * 8);
            bulk_g2s(sbase + s * STAGE_B + A_STAGE, bP, B_STAGE, mfull + s * 8);
        }
    }

    int g = lane >> 3, sub = lane & 7;
    int rowA_base = wm * 64 + ((g & 1) << 3) + sub;
    int kcA_base  = g >> 1;
    int rowB_base = wn * 32 + ((g >> 1) << 3) + sub;
    int kcB_base  = g & 1;

    float acc[4][4][4];
    #pragma unroll
    for (int i = 0; i < 4; i++)
        #pragma unroll
        for (int j = 0; j < 4; j++)
            #pragma unroll
            for (int t = 0; t < 4; t++) acc[i][j][t] = 0.f;

    int rlo = lane >> 2;
    int cpair = (lane & 3) * 2;
    int cIn = 0;
    int unitIdx = 0;

    for (int q = 0; q < Qtot; q++) {
        int slot = q & 3;
        if (wid == 0) {
            int qp = q + STG - 1;
            if (qp < Qtot) {
                int sp = qp & 3;
                if (qp >= STG) mbar_wait(mempty + sp * 8, ((qp >> 2) + 1) & 1);
                if (lane == 0) {
                    int u = bid + NSM * (qp / UCHUNKS);
                    int t = u >> 3;
                    int cc = (u & 7) * UCHUNKS + (qp % UCHUNKS);
                    const char* aP = (const char*)g_u  + ((size_t)(t >> 3) * CHUNKS + cc) * A_STAGE;
                    const char* bP = (const char*)g_bt + ((size_t)(t & 7)  * CHUNKS + cc) * B_STAGE;
                    mbar_expect_tx(mfull + sp * 8, STAGE_B);
                    bulk_g2s(sbase + sp * STAGE_B,           aP, A_STAGE, mfull + sp * 8);
                    bulk_g2s(sbase + sp * STAGE_B + A_STAGE, bP, B_STAGE, mfull + sp * 8);
                }
            }
        }

        mbar_wait(mfull + slot * 8, (q >> 2) & 1);

        uint32_t aS = sbase + slot * STAGE_B;
        uint32_t bS = aS + A_STAGE;
        #pragma unroll
        for (int ks = 0; ks < 4; ks++) {
            uint32_t afr[4][4], bfr[2][4];
            #pragma unroll
            for (int qq = 0; qq < 2; qq++) {
                int row = rowB_base + qq * 16;
                ldsm_x4(bfr[qq], bS + sw_off(row, ks * 2 + kcB_base));
            }
            #pragma unroll
            for (int mt = 0; mt < 4; mt++) {
                int row = rowA_base + mt * 16;
                ldsm_x4(afr[mt], aS + sw_off(row, ks * 2 + kcA_base));
            }
            #pragma unroll
            for (int mt = 0; mt < 4; mt++)
                #pragma unroll
                for (int nt = 0; nt < 4; nt++)
                    mma16816(acc[mt][nt], afr[mt], &bfr[nt >> 1][(nt & 1) * 2]);
        }
        if (lane == 0) mbar_arrive(mempty + slot * 8);

        if (++cIn == UCHUNKS) {
            cIn = 0;
            int u = bid + NSM * unitIdx;
            unitIdx++;
            float* dst = g_part + (size_t)u * TILE_ELEMS;
            #pragma unroll
            for (int mt = 0; mt < 4; mt++) {
                #pragma unroll
                for (int nt = 0; nt < 4; nt++) {
                    int col = wn * 32 + nt * 8 + cpair;
                    int row0 = wm * 64 + mt * 16 + rlo;
                    *reinterpret_cast<float2*>(dst + (size_t)row0 * BN + col) =
                        make_float2(acc[mt][nt][0], acc[mt][nt][1]);
                    *reinterpret_cast<float2*>(dst + (size_t)(row0 + 8) * BN + col) =
                        make_float2(acc[mt][nt][2], acc[mt][nt][3]);
                    acc[mt][nt][0] = acc[mt][nt][1] = acc[mt][nt][2] = acc[mt][nt][3] = 0.f;
                }
            }
        }
    }
}

// ==================== kernel 3: fused reduce + bias + relu + head, 1 sample/block ====================
// 2048 blocks x 256 threads. Each thread handles 8 h-values: sums 8 split-K partials
// (lane-consecutive col -> one 128B line per slice), bias+relu, 10-class FMA.
__global__ void __launch_bounds__(256) k_final(const float* __restrict__ bv,
                                               const float* __restrict__ Wo,
                                               const float* __restrict__ bo,
                                               float* __restrict__ out) {
    int n = blockIdx.x;
    int tid = threadIdx.x;
    int lane = tid & 31, wid = tid >> 5;
    int mb = n >> 7, row = n & 127;

    float acc[CLASSES];
    #pragma unroll
    for (int c = 0; c < CLASSES; c++) acc[c] = 0.f;

    #pragma unroll 1
    for (int i = 0; i < HIDDEN / 256; i++) {
        int h = tid + i * 256;
        int nb = h >> 8, col = h & 255;
        const float* p = g_part + ((size_t)(mb * 8 + nb) * KSLICES) * TILE_ELEMS
                                + (size_t)row * BN + col;
        float v = __ldg(bv + h);
        #pragma unroll
        for (int ks = 0; ks < KSLICES; ks++)
            v += __ldg(p + (size_t)ks * TILE_ELEMS);
        v = fmaxf(v, 0.f);
        const float2* wrow = reinterpret_cast<const float2*>(Wo + (size_t)h * CLASSES);
        #pragma unroll
        for (int c2 = 0; c2 < CLASSES / 2; c2++) {
            float2 ww = __ldg(wrow + c2);
            acc[c2 * 2]     = fmaf(v, ww.x, acc[c2 * 2]);
            acc[c2 * 2 + 1] = fmaf(v, ww.y, acc[c2 * 2 + 1]);
        }
    }
    #pragma unroll
    for (int c = 0; c < CLASSES; c++)
        #pragma unroll
        for (int o = 16; o > 0; o >>= 1)
            acc[c] += __shfl_xor_sync(0xffffffffu, acc[c], o);

    __shared__ float part[8][CLASSES];
    if (lane == 0) {
        #pragma unroll
        for (int c = 0; c < CLASSES; c++) part[wid][c] = acc[c];
    }
    __syncthreads();
    if (tid < CLASSES) {
        float s = 0.f;
        #pragma unroll
        for (int w = 0; w < 8; w++) s += part[w][tid];
        out[(size_t)n * CLASSES + tid] = s + bo[tid];
    }
}

// ==================== launch ====================
extern "C" void kernel_launch(void* const* d_in, const int* in_sizes, int n_in,
                              void* d_out, int out_size) {
    const float* x  = (const float*)d_in[0];
    const float* Wu = (const float*)d_in[1];
    const float* bu = (const float*)d_in[2];
    const float* Wv = (const float*)d_in[3];
    const float* bv = (const float*)d_in[4];
    const float* Wo = (const float*)d_in[5];
    const float* bo = (const float*)d_in[6];
    float* out = (float*)d_out;

    cudaFuncSetAttribute(k_gemm, cudaFuncAttributeMaxDynamicSharedMemorySize, SMEM_GEMM);

    k_prep<<<CHUNKS + CONV_BLOCKS, 256>>>(x, Wu, bu, Wv);
    k_gemm<<<NSM, 512, SMEM_GEMM>>>();
    k_final<<<N_SAMPLES, 256>>>(bv, Wo, bo, out);
}